// round 5
// baseline (speedup 1.0000x reference)
#include <cuda_runtime.h>

#define THREADS 256
#define NBN 2456                     // B*N = 8*307
#define OUT_ELEMS 10059776           // B*N*L*DM
#define TOTAL_ELEMS 50298880         // out + scores
#define SMEM_FLOATS 37184            // 148,736 bytes

// copy 4096 floats (64x64 tile) with float4
__device__ __forceinline__ void copy4k(float* dst, const float* __restrict__ src, int tid) {
    float4* d = (float4*)dst;
    const float4* s = (const float4*)src;
#pragma unroll
    for (int i = 0; i < 4; i++) d[tid + i * THREADS] = __ldg(&s[tid + i * THREADS]);
}

// dst[64x64] = Xs[64x64] @ Ws[64x64]  (+ resid), thread t -> row r=t/4, cols cg..cg+15
__device__ __forceinline__ void gemm64(const float* __restrict__ Xs,
                                       const float* __restrict__ Ws,
                                       float* __restrict__ dst,
                                       const float* __restrict__ resid,
                                       int r, int cg) {
    float acc[16];
#pragma unroll
    for (int j = 0; j < 16; j++) acc[j] = 0.f;
#pragma unroll 4
    for (int k = 0; k < 64; k++) {
        float x = Xs[(r << 6) + k];
#pragma unroll
        for (int j = 0; j < 4; j++) {
            float4 w = *(const float4*)(Ws + (k << 6) + cg + (j << 2));
            acc[4 * j + 0] = fmaf(x, w.x, acc[4 * j + 0]);
            acc[4 * j + 1] = fmaf(x, w.y, acc[4 * j + 1]);
            acc[4 * j + 2] = fmaf(x, w.z, acc[4 * j + 2]);
            acc[4 * j + 3] = fmaf(x, w.w, acc[4 * j + 3]);
        }
    }
#pragma unroll
    for (int j = 0; j < 16; j++) {
        float v = acc[j];
        if (resid) v += resid[(r << 6) + cg + j];
        dst[(r << 6) + cg + j] = v;
    }
}

__global__ __launch_bounds__(THREADS, 1)
void mta_kernel(const float* __restrict__ gQ, const float* __restrict__ gK,
                const float* __restrict__ gV, const float* __restrict__ gMask,
                const float* __restrict__ gRes,
                const float* __restrict__ gWq, const float* __restrict__ gWk,
                const float* __restrict__ gWv, const float* __restrict__ gWfc,
                const float* __restrict__ gScale, const float* __restrict__ gBias,
                float* __restrict__ gOut, float* __restrict__ gScores,
                int write_scores) {
    extern __shared__ float sm[];
    float* Xs = sm;            // 4096  input tile / residual
    float* Ws = sm + 4096;     // 4096  weight tile
    float* Qs = sm + 8192;     // 4096  Q, later context
    float* Ks = sm + 12288;    // 4096  K, later y (pre-LN)
    float* Vs = sm + 16384;    // 4096  V
    float* Sc = sm + 20480;    // 16640 scores [h][q][k], pitch 65
    float* mrow = sm + 37120;  // 64    attn_mask row

    const int tid = threadIdx.x;
    const int bn = blockIdx.x;
    const float* xq = gQ + ((size_t)bn << 12);
    const float* xk = gK + ((size_t)bn << 12);
    const float* xv = gV + ((size_t)bn << 12);
    const float* res = gRes + ((size_t)bn << 14);

    if (tid < 64) mrow[tid] = gMask[(bn << 6) + tid];

    const int r  = tid >> 2;
    const int cg = (tid & 3) << 4;

    // ---- Q/K/V projections ----
    copy4k(Xs, xq, tid); copy4k(Ws, gWq, tid); __syncthreads();
    gemm64(Xs, Ws, Qs, nullptr, r, cg);        __syncthreads();
    copy4k(Xs, xk, tid); copy4k(Ws, gWk, tid); __syncthreads();
    gemm64(Xs, Ws, Ks, nullptr, r, cg);        __syncthreads();
    copy4k(Xs, xv, tid); copy4k(Ws, gWv, tid); __syncthreads();
    gemm64(Xs, Ws, Vs, nullptr, r, cg);        __syncthreads();

    // ---- scores = Q.K^T / 4  (thread = (h,q), loops k; K row broadcast per warp) ----
    {
        const int h = tid >> 6, q = tid & 63;
        float qv[16];
#pragma unroll
        for (int j = 0; j < 4; j++) {
            float4 t = *(const float4*)(Qs + (q << 6) + (h << 4) + (j << 2));
            qv[4 * j] = t.x; qv[4 * j + 1] = t.y; qv[4 * j + 2] = t.z; qv[4 * j + 3] = t.w;
        }
        float* srow = Sc + ((h << 6) + q) * 65;
#pragma unroll 4
        for (int k = 0; k < 64; k++) {
            float s = 0.f;
#pragma unroll
            for (int j = 0; j < 4; j++) {
                float4 kv = *(const float4*)(Ks + (k << 6) + (h << 4) + (j << 2));
                s = fmaf(qv[4 * j + 0], kv.x, s);
                s = fmaf(qv[4 * j + 1], kv.y, s);
                s = fmaf(qv[4 * j + 2], kv.z, s);
                s = fmaf(qv[4 * j + 3], kv.w, s);
            }
            srow[k] = s * 0.25f;
        }
    }
    __syncthreads();

    // ---- add res_att, apply mask, emit scores output (coalesced float4) ----
    {
        const float4* r4 = (const float4*)res;
        float4* s4out = write_scores ? (float4*)(gScores + ((size_t)bn << 14)) : nullptr;
#pragma unroll
        for (int ii = 0; ii < 16; ii++) {
            int i4 = tid + ii * THREADS;
            int i = i4 << 2;
            int h = i >> 12, q = (i >> 6) & 63, k = i & 63;
            float4 rv = __ldg(&r4[i4]);
            float* p = Sc + ((h << 6) + q) * 65 + k;
            bool m = mrow[q] > 0.5f;
            float4 v;
            v.x = m ? -1e9f : p[0] + rv.x;
            v.y = m ? -1e9f : p[1] + rv.y;
            v.z = m ? -1e9f : p[2] + rv.z;
            v.w = m ? -1e9f : p[3] + rv.w;
            p[0] = v.x; p[1] = v.y; p[2] = v.z; p[3] = v.w;
            if (s4out) s4out[i4] = v;
        }
    }
    __syncthreads();

    // ---- softmax over q (axis=3!) per (h,k) column; thread = one column ----
    {
        const int h = tid >> 6, k = tid & 63;
        float* col = Sc + (h << 6) * 65 + k;
        float mx = -3.4e38f;
#pragma unroll 4
        for (int q = 0; q < 64; q++) mx = fmaxf(mx, col[q * 65]);
        float ssum = 0.f;
#pragma unroll 4
        for (int q = 0; q < 64; q++) {
            float e = __expf(col[q * 65] - mx);
            col[q * 65] = e;
            ssum += e;
        }
        float inv = 1.0f / ssum;
#pragma unroll 4
        for (int q = 0; q < 64; q++) col[q * 65] *= inv;
    }
    __syncthreads();

    // ---- context = attn @ V  (thread = (q,h), 16 accumulators over d) ----
    {
        const int q = tid >> 2, h = tid & 3;
        const float* arow = Sc + ((h << 6) + q) * 65;
        float acc[16];
#pragma unroll
        for (int j = 0; j < 16; j++) acc[j] = 0.f;
#pragma unroll 4
        for (int k = 0; k < 64; k++) {
            float a = arow[k];
#pragma unroll
            for (int j = 0; j < 4; j++) {
                float4 v = *(const float4*)(Vs + (k << 6) + (h << 4) + (j << 2));
                acc[4 * j + 0] = fmaf(a, v.x, acc[4 * j + 0]);
                acc[4 * j + 1] = fmaf(a, v.y, acc[4 * j + 1]);
                acc[4 * j + 2] = fmaf(a, v.z, acc[4 * j + 2]);
                acc[4 * j + 3] = fmaf(a, v.w, acc[4 * j + 3]);
            }
        }
#pragma unroll
        for (int j = 0; j < 16; j++) Qs[(q << 6) + (h << 4) + j] = acc[j];
    }
    // stage FC weight + residual input while context finishes elsewhere
    copy4k(Xs, xq, tid);
    copy4k(Ws, gWfc, tid);
    __syncthreads();

    // ---- y = context @ W_fc + input_Q  (into Ks) ----
    gemm64(Qs, Ws, Ks, Xs, r, cg);
    __syncthreads();

    // ---- LayerNorm per row (warp-per-row, shfl reductions) ----
    {
        const int w = tid >> 5, lane = tid & 31;
        float s0 = __ldg(&gScale[lane]),      s1 = __ldg(&gScale[lane + 32]);
        float b0 = __ldg(&gBias[lane]),       b1 = __ldg(&gBias[lane + 32]);
        float* outp = gOut + ((size_t)bn << 12);
#pragma unroll
        for (int rr = w; rr < 64; rr += 8) {
            float v0 = Ks[(rr << 6) + lane];
            float v1 = Ks[(rr << 6) + lane + 32];
            float s = v0 + v1;
#pragma unroll
            for (int o = 16; o > 0; o >>= 1) s += __shfl_xor_sync(0xffffffffu, s, o);
            float mu = s * 0.015625f;
            float d0 = v0 - mu, d1 = v1 - mu;
            float vv = d0 * d0 + d1 * d1;
#pragma unroll
            for (int o = 16; o > 0; o >>= 1) vv += __shfl_xor_sync(0xffffffffu, vv, o);
            float inv = rsqrtf(vv * 0.015625f + 1e-5f);
            outp[(rr << 6) + lane]      = fmaf(d0 * inv, s0, b0);
            outp[(rr << 6) + lane + 32] = fmaf(d1 * inv, s1, b1);
        }
    }
}

extern "C" void kernel_launch(void* const* d_in, const int* in_sizes, int n_in,
                              void* d_out, int out_size) {
    const float* gQ = (const float*)d_in[0];
    const float* gK = (const float*)d_in[1];
    const float* gV = (const float*)d_in[2];
    const float* gM = (const float*)d_in[3];
    const float* gR = (const float*)d_in[4];
    const float* wq = (const float*)d_in[5];
    const float* wk = (const float*)d_in[6];
    const float* wv = (const float*)d_in[7];
    const float* wf = (const float*)d_in[8];
    const float* ls = (const float*)d_in[9];
    const float* lb = (const float*)d_in[10];
    float* out = (float*)d_out;

    int write_scores = (out_size >= (int)TOTAL_ELEMS) ? 1 : 0;
    float* scores = out + OUT_ELEMS;

    size_t smem = (size_t)SMEM_FLOATS * sizeof(float);
    cudaFuncSetAttribute(mta_kernel, cudaFuncAttributeMaxDynamicSharedMemorySize, (int)smem);
    mta_kernel<<<NBN, THREADS, smem>>>(gQ, gK, gV, gM, gR, wq, wk, wv, wf, ls, lb,
                                       out, scores, write_scores);
}

// round 6
// speedup vs baseline: 1.9713x; 1.9713x over previous
#include <cuda_runtime.h>

#define THREADS 256
#define NBN 2456                     // B*N = 8*307
#define OUT_ELEMS 10059776           // B*N*L*DM
#define TOTAL_ELEMS 50298880         // out + scores
#define XP 68                        // padded pitch for X/ctx operand (bank-shift 4/row)
// smem layout (floats): A[64*68]=4352 | B[64*64]=4096 | C[64*64]=4096 | Sc[4*64*64]=16384
#define SM_A 0
#define SM_B 4352
#define SM_C 8448
#define SM_SC 12544
#define SMEM_FLOATS 28928            // 115,712 bytes -> 2 CTAs/SM

// copy 64x64 row-major tile into pitch-68 smem (X operand role)
__device__ __forceinline__ void copyX(float* __restrict__ A, const float* __restrict__ src, int tid) {
#pragma unroll
    for (int i = 0; i < 4; i++) {
        int i4 = tid + i * THREADS;
        float4 v = __ldg((const float4*)src + i4);
        int row = i4 >> 4, c4 = (i4 & 15) << 2;
        *(float4*)(A + row * XP + c4) = v;
    }
}

// copy 64x64 tile linearly into pitch-64 smem (W operand role)
__device__ __forceinline__ void copyW(float* __restrict__ Bm, const float* __restrict__ src, int tid) {
    float4* d = (float4*)Bm;
    const float4* s = (const float4*)src;
#pragma unroll
    for (int i = 0; i < 4; i++) d[tid + i * THREADS] = __ldg(&s[tid + i * THREADS]);
}

// dst[64x64,p64] = Xs[64x64,p68] @ Ws[64x64,p64] (+ optional gmem resid)
// thread: row r = tid>>2, cols c0+16j (c0=(tid&3)*4, j=0..3) -> conflict-free LDS
__device__ __forceinline__ void gemm_tile(const float* __restrict__ Xs,
                                          const float* __restrict__ Ws,
                                          float* __restrict__ dst,
                                          const float* __restrict__ gresid,
                                          int r, int c0) {
    float acc[16];
#pragma unroll
    for (int j = 0; j < 16; j++) acc[j] = 0.f;
#pragma unroll 4
    for (int k4 = 0; k4 < 64; k4 += 4) {
        float4 x = *(const float4*)(Xs + r * XP + k4);
#pragma unroll
        for (int kk = 0; kk < 4; kk++) {
            float xv = (kk == 0) ? x.x : (kk == 1) ? x.y : (kk == 2) ? x.z : x.w;
            const float* wrow = Ws + ((k4 + kk) << 6) + c0;
#pragma unroll
            for (int j = 0; j < 4; j++) {
                float4 w = *(const float4*)(wrow + (j << 4));
                acc[4 * j + 0] = fmaf(xv, w.x, acc[4 * j + 0]);
                acc[4 * j + 1] = fmaf(xv, w.y, acc[4 * j + 1]);
                acc[4 * j + 2] = fmaf(xv, w.z, acc[4 * j + 2]);
                acc[4 * j + 3] = fmaf(xv, w.w, acc[4 * j + 3]);
            }
        }
    }
#pragma unroll
    for (int j = 0; j < 4; j++) {
        float4 v = make_float4(acc[4 * j], acc[4 * j + 1], acc[4 * j + 2], acc[4 * j + 3]);
        if (gresid) {
            float4 rr = __ldg((const float4*)(gresid + (r << 6) + c0 + (j << 4)));
            v.x += rr.x; v.y += rr.y; v.z += rr.z; v.w += rr.w;
        }
        *(float4*)(dst + (r << 6) + c0 + (j << 4)) = v;
    }
}

__global__ __launch_bounds__(THREADS, 2)
void mta_kernel(const float* __restrict__ gQ, const float* __restrict__ gK,
                const float* __restrict__ gV, const float* __restrict__ gMask,
                const float* __restrict__ gRes,
                const float* __restrict__ gWq, const float* __restrict__ gWk,
                const float* __restrict__ gWv, const float* __restrict__ gWfc,
                const float* __restrict__ gScale, const float* __restrict__ gBias,
                float* __restrict__ gOut, float* __restrict__ gScores,
                int write_scores) {
    extern __shared__ float sm[];
    float* A  = sm + SM_A;    // X tiles (pitch 68), later context
    float* Bm = sm + SM_B;    // weight tile (pitch 64)
    float* C  = sm + SM_C;    // K, then V, then y (pitch 64)
    float* Sc = sm + SM_SC;   // scores [h][q][k] pitch 64 (linear)

    const int tid = threadIdx.x;
    const int bn = blockIdx.x;
    const float* xq = gQ + ((size_t)bn << 12);
    const float* xk = gK + ((size_t)bn << 12);
    const float* xv = gV + ((size_t)bn << 12);
    const float* res = gRes + ((size_t)bn << 14);

    const int r  = tid >> 2;
    const int c0 = (tid & 3) << 2;
    const int h  = tid >> 6;
    const int q  = tid & 63;

    // P0: stage Xk, Wk
    copyX(A, xk, tid); copyW(Bm, gWk, tid);
    __syncthreads();
    // P1: K = Xk @ Wk -> C
    gemm_tile(A, Bm, C, nullptr, r, c0);
    __syncthreads();
    // P2: stage Xq, Wq
    copyX(A, xq, tid); copyW(Bm, gWq, tid);
    __syncthreads();

    // P3: Q row in registers (thread = (h,q) owns Q[q][h*16..+15]), then QK^T -> Sc
    {
        float qv[16];
#pragma unroll
        for (int j = 0; j < 16; j++) qv[j] = 0.f;
#pragma unroll 4
        for (int k4 = 0; k4 < 64; k4 += 4) {
            float4 x = *(const float4*)(A + q * XP + k4);
#pragma unroll
            for (int kk = 0; kk < 4; kk++) {
                float xv2 = (kk == 0) ? x.x : (kk == 1) ? x.y : (kk == 2) ? x.z : x.w;
                const float* wrow = Bm + ((k4 + kk) << 6) + (h << 4);
#pragma unroll
                for (int j = 0; j < 4; j++) {
                    float4 w = *(const float4*)(wrow + (j << 2));
                    qv[4 * j + 0] = fmaf(xv2, w.x, qv[4 * j + 0]);
                    qv[4 * j + 1] = fmaf(xv2, w.y, qv[4 * j + 1]);
                    qv[4 * j + 2] = fmaf(xv2, w.z, qv[4 * j + 2]);
                    qv[4 * j + 3] = fmaf(xv2, w.w, qv[4 * j + 3]);
                }
            }
        }
        // scores row: Sc[h][q][:] = (qv . K[k][h*16..]) / 4   (K rows broadcast: warp has h fixed)
        float* srow = Sc + (h << 12) + (q << 6);
#pragma unroll 2
        for (int k4 = 0; k4 < 64; k4 += 4) {
            float sbuf[4];
#pragma unroll
            for (int kk = 0; kk < 4; kk++) {
                const float* krow = C + ((k4 + kk) << 6) + (h << 4);
                float s = 0.f;
#pragma unroll
                for (int j = 0; j < 4; j++) {
                    float4 kv = *(const float4*)(krow + (j << 2));
                    s = fmaf(qv[4 * j + 0], kv.x, s);
                    s = fmaf(qv[4 * j + 1], kv.y, s);
                    s = fmaf(qv[4 * j + 2], kv.z, s);
                    s = fmaf(qv[4 * j + 3], kv.w, s);
                }
                sbuf[kk] = s * 0.25f;
            }
            *(float4*)(srow + k4) = make_float4(sbuf[0], sbuf[1], sbuf[2], sbuf[3]);
        }
    }
    __syncthreads();

    // P4: stage Xv, Wv (LDG latency overlapped) + add res_att, mask, emit scores output
    copyX(A, xv, tid); copyW(Bm, gWv, tid);
    {
        const float4* r4 = (const float4*)res;
        float4* sc4 = (float4*)Sc;
        float4* s4out = write_scores ? (float4*)(gScores + ((size_t)bn << 14)) : nullptr;
#pragma unroll
        for (int ii = 0; ii < 16; ii++) {
            int i4 = tid + ii * THREADS;
            int qq = (i4 >> 4) & 63;
            bool m = __ldg(gMask + (bn << 6) + qq) > 0.5f;
            float4 rv = __ldg(&r4[i4]);
            float4 p = sc4[i4];
            float4 v;
            v.x = m ? -1e9f : p.x + rv.x;
            v.y = m ? -1e9f : p.y + rv.y;
            v.z = m ? -1e9f : p.z + rv.z;
            v.w = m ? -1e9f : p.w + rv.w;
            sc4[i4] = v;
            if (s4out) s4out[i4] = v;
        }
    }
    __syncthreads();

    // P5: V = Xv @ Wv -> C (overwrites K) ; softmax over q per (h,k) column
    gemm_tile(A, Bm, C, nullptr, r, c0);
    {
        float* col = Sc + (h << 12) + q;   // here (h, k=q): warp spans k -> conflict-free
        float mx = -3.4e38f;
#pragma unroll 8
        for (int qq = 0; qq < 64; qq++) mx = fmaxf(mx, col[qq << 6]);
        float ssum = 0.f;
#pragma unroll 8
        for (int qq = 0; qq < 64; qq++) {
            float e = __expf(col[qq << 6] - mx);
            col[qq << 6] = e;
            ssum += e;
        }
        float inv = 1.0f / ssum;
#pragma unroll 8
        for (int qq = 0; qq < 64; qq++) col[qq << 6] *= inv;
    }
    __syncthreads();

    // P6: ctx = attn @ V -> A (pitch 68) ; stage Wfc -> Bm
    copyW(Bm, gWfc, tid);
    {
        const float* arow = Sc + (h << 12) + (q << 6);
        float acc[16];
#pragma unroll
        for (int j = 0; j < 16; j++) acc[j] = 0.f;
#pragma unroll 4
        for (int k4 = 0; k4 < 64; k4 += 4) {
            float4 a = *(const float4*)(arow + k4);
#pragma unroll
            for (int kk = 0; kk < 4; kk++) {
                float av = (kk == 0) ? a.x : (kk == 1) ? a.y : (kk == 2) ? a.z : a.w;
                const float* vrow = C + ((k4 + kk) << 6) + (h << 4);  // broadcast (h fixed/warp)
#pragma unroll
                for (int j = 0; j < 4; j++) {
                    float4 vv = *(const float4*)(vrow + (j << 2));
                    acc[4 * j + 0] = fmaf(av, vv.x, acc[4 * j + 0]);
                    acc[4 * j + 1] = fmaf(av, vv.y, acc[4 * j + 1]);
                    acc[4 * j + 2] = fmaf(av, vv.z, acc[4 * j + 2]);
                    acc[4 * j + 3] = fmaf(av, vv.w, acc[4 * j + 3]);
                }
            }
        }
#pragma unroll
        for (int j = 0; j < 4; j++)
            *(float4*)(A + q * XP + (h << 4) + (j << 2)) =
                make_float4(acc[4 * j], acc[4 * j + 1], acc[4 * j + 2], acc[4 * j + 3]);
    }
    __syncthreads();

    // P7: y = ctx @ W_fc + input_Q (resid via LDG) -> C
    gemm_tile(A, Bm, C, xq, r, c0);
    __syncthreads();

    // P8: LayerNorm per row (warp-per-row) -> gOut
    {
        const int w = tid >> 5, lane = tid & 31;
        float s0 = __ldg(&gScale[lane]), s1 = __ldg(&gScale[lane + 32]);
        float b0 = __ldg(&gBias[lane]),  b1 = __ldg(&gBias[lane + 32]);
        float* outp = gOut + ((size_t)bn << 12);
#pragma unroll
        for (int rr = w; rr < 64; rr += 8) {
            float v0 = C[(rr << 6) + lane];
            float v1 = C[(rr << 6) + lane + 32];
            float s = v0 + v1;
#pragma unroll
            for (int o = 16; o > 0; o >>= 1) s += __shfl_xor_sync(0xffffffffu, s, o);
            float mu = s * 0.015625f;
            float d0 = v0 - mu, d1 = v1 - mu;
            float vv = d0 * d0 + d1 * d1;
#pragma unroll
            for (int o = 16; o > 0; o >>= 1) vv += __shfl_xor_sync(0xffffffffu, vv, o);
            float inv = rsqrtf(vv * 0.015625f + 1e-5f);
            outp[(rr << 6) + lane]      = fmaf(d0 * inv, s0, b0);
            outp[(rr << 6) + lane + 32] = fmaf(d1 * inv, s1, b1);
        }
    }
}

extern "C" void kernel_launch(void* const* d_in, const int* in_sizes, int n_in,
                              void* d_out, int out_size) {
    const float* gQ = (const float*)d_in[0];
    const float* gK = (const float*)d_in[1];
    const float* gV = (const float*)d_in[2];
    const float* gM = (const float*)d_in[3];
    const float* gR = (const float*)d_in[4];
    const float* wq = (const float*)d_in[5];
    const float* wk = (const float*)d_in[6];
    const float* wv = (const float*)d_in[7];
    const float* wf = (const float*)d_in[8];
    const float* ls = (const float*)d_in[9];
    const float* lb = (const float*)d_in[10];
    float* out = (float*)d_out;

    int write_scores = (out_size >= (int)TOTAL_ELEMS) ? 1 : 0;
    float* scores = out + OUT_ELEMS;

    size_t smem = (size_t)SMEM_FLOATS * sizeof(float);
    cudaFuncSetAttribute(mta_kernel, cudaFuncAttributeMaxDynamicSharedMemorySize, (int)smem);
    mta_kernel<<<NBN, THREADS, smem>>>(gQ, gK, gV, gM, gR, wq, wk, wv, wf, ls, lb,
                                       out, scores, write_scores);
}

// round 9
// speedup vs baseline: 4.0658x; 2.0624x over previous
#include <cuda_runtime.h>

#define THREADS 256
#define NBN 2456                     // B*N = 8*307
#define OUT_ELEMS 10059776           // B*N*L*DM
#define TOTAL_ELEMS 50298880         // out + scores
#define AP 68                        // pitch of A (X/ctx) buffer: lane-per-row conflict-free
// smem floats: A[64*68=4352] | Bm[4096] | C[4096] | Sc[16384]  = 28928 fl = 115,712 B
#define SM_A 0
#define SM_B 4352
#define SM_C 8448
#define SM_SC 12544
#define SMEM_FLOATS 28928            // 2 CTAs/SM (proven in R5)

__device__ __forceinline__ float elem4(const float4 v, int kk) {
    return (kk == 0) ? v.x : (kk == 1) ? v.y : (kk == 2) ? v.z : v.w;
}

// Sc rotation layout: head h, row q, 16B-granule g (0..15) -> slot (g+q)&15.
// Same function used by QK writer, softmax, and AV reader.
__device__ __forceinline__ int sidxS(int h, int q, int g) {
    return (h << 12) + (q << 6) + (((g + q) & 15) << 2);
}

// stage 64x64 row-major tile -> A (pitch AP)
__device__ __forceinline__ void stageX(float* __restrict__ A, const float* __restrict__ src, int tid) {
#pragma unroll
    for (int i = 0; i < 4; i++) {
        int i4 = tid + i * THREADS;
        float4 v = __ldg((const float4*)src + i4);
        *(float4*)(A + (i4 >> 4) * AP + ((i4 & 15) << 2)) = v;
    }
}

// stage 64x64 tile -> linear pitch-64 smem (weights / broadcast-read operands)
__device__ __forceinline__ void stageW(float* __restrict__ Bm, const float* __restrict__ src, int tid) {
#pragma unroll
    for (int i = 0; i < 4; i++)
        ((float4*)Bm)[tid + i * THREADS] = __ldg((const float4*)src + tid + i * THREADS);
}

// dst[64x64,p64] = A[64x64,pAP] @ Bm[64x64,p64] (+ optional gmem residual, pitch 64)
// thread (ty,tx): rows 4ty..+3 (x-loads phase-broadcast), cols 4tx..+3 (w-loads phase-coalesced)
__device__ __forceinline__ void gemm44(const float* __restrict__ A, const float* __restrict__ Bm,
                                       float* __restrict__ dst,
                                       const float* __restrict__ gresid, int ty, int tx) {
    const int r0 = ty << 2, c0 = tx << 2;
    float acc[4][4];
#pragma unroll
    for (int i = 0; i < 4; i++)
#pragma unroll
        for (int j = 0; j < 4; j++) acc[i][j] = 0.f;
#pragma unroll 4
    for (int k4 = 0; k4 < 64; k4 += 4) {
        float4 xr[4], wv[4];
#pragma unroll
        for (int i = 0; i < 4; i++) xr[i] = *(const float4*)(A + (r0 + i) * AP + k4);
#pragma unroll
        for (int kk = 0; kk < 4; kk++) wv[kk] = *(const float4*)(Bm + ((k4 + kk) << 6) + c0);
#pragma unroll
        for (int kk = 0; kk < 4; kk++)
#pragma unroll
            for (int i = 0; i < 4; i++) {
                float a = elem4(xr[i], kk);
                acc[i][0] = fmaf(a, wv[kk].x, acc[i][0]);
                acc[i][1] = fmaf(a, wv[kk].y, acc[i][1]);
                acc[i][2] = fmaf(a, wv[kk].z, acc[i][2]);
                acc[i][3] = fmaf(a, wv[kk].w, acc[i][3]);
            }
    }
#pragma unroll
    for (int i = 0; i < 4; i++) {
        float4 v = make_float4(acc[i][0], acc[i][1], acc[i][2], acc[i][3]);
        if (gresid) {
            float4 rr = __ldg((const float4*)(gresid + ((r0 + i) << 6) + c0));
            v.x += rr.x; v.y += rr.y; v.z += rr.z; v.w += rr.w;
        }
        *(float4*)(dst + ((r0 + i) << 6) + c0) = v;
    }
}

__global__ __launch_bounds__(THREADS, 2)
void mta_kernel(const float* __restrict__ gQ, const float* __restrict__ gK,
                const float* __restrict__ gV, const float* __restrict__ gMask,
                const float* __restrict__ gRes,
                const float* __restrict__ gWq, const float* __restrict__ gWk,
                const float* __restrict__ gWv, const float* __restrict__ gWfc,
                const float* __restrict__ gScale, const float* __restrict__ gBias,
                float* __restrict__ gOut, float* __restrict__ gScores,
                int write_scores) {
    extern __shared__ float sm[];
    float* A  = sm + SM_A;    // Xk / Xq / Xv / ctx   (pitch AP=68)
    float* Bm = sm + SM_B;    // weight tile          (pitch 64, broadcast reads)
    float* C  = sm + SM_C;    // K -> V -> y          (pitch 64)
    float* Sc = sm + SM_SC;   // scores, rotation layout via sidxS

    const int tid = threadIdx.x;
    const int bn = blockIdx.x;
    const float* xq = gQ + ((size_t)bn << 12);
    const float* xk = gK + ((size_t)bn << 12);
    const float* xv = gV + ((size_t)bn << 12);

    const int ty = tid >> 4, tx = tid & 15;
    const int h  = tid >> 6;           // warp-uniform
    const int q  = tid & 63;           // lane-distinct

    // P1: stage Xk, Wk
    stageX(A, xk, tid); stageW(Bm, gWk, tid);
    __syncthreads();
    // P2: K = Xk @ Wk -> C
    gemm44(A, Bm, C, nullptr, ty, tx);
    __syncthreads();
    // P3: stage Xq, Wq
    stageX(A, xq, tid); stageW(Bm, gWq, tid);
    __syncthreads();

    // P4: Q row into registers (thread=(h,q)); weight reads broadcast, X reads conflict-free @AP
    float qv[16];
    {
#pragma unroll
        for (int j = 0; j < 16; j++) qv[j] = 0.f;
#pragma unroll 4
        for (int d4 = 0; d4 < 64; d4 += 4) {
            float4 x = *(const float4*)(A + q * AP + d4);
#pragma unroll
            for (int kk = 0; kk < 4; kk++) {
                float xs = elem4(x, kk);
                const float* wr = Bm + ((d4 + kk) << 6) + (h << 4);
#pragma unroll
                for (int j = 0; j < 4; j++) {
                    float4 w = *(const float4*)(wr + (j << 2));
                    qv[4 * j + 0] = fmaf(xs, w.x, qv[4 * j + 0]);
                    qv[4 * j + 1] = fmaf(xs, w.y, qv[4 * j + 1]);
                    qv[4 * j + 2] = fmaf(xs, w.z, qv[4 * j + 2]);
                    qv[4 * j + 3] = fmaf(xs, w.w, qv[4 * j + 3]);
                }
            }
        }
    }
    __syncthreads();   // A, Bm free

    // P5: stage Xv, Wv (LDGs overlap QK) + QK with fused epilogue -> Sc + gmem scores
    stageX(A, xv, tid); stageW(Bm, gWv, tid);
    {
        const bool msk = __ldg(gMask + (bn << 6) + q) > 0.5f;
        const float4* res4 = (const float4*)(gRes + ((size_t)bn << 14)) + (((h << 6) + q) << 4);
        float4* sout = write_scores
            ? (float4*)(gScores + ((size_t)bn << 14)) + (((h << 6) + q) << 4) : nullptr;
#pragma unroll 2
        for (int g = 0; g < 16; g++) {       // k granule: k = 4g..4g+3
            float sb[4];
#pragma unroll
            for (int kk = 0; kk < 4; kk++) {
                const float* krow = C + (((g << 2) + kk) << 6) + (h << 4);  // broadcast
                float s = 0.f;
#pragma unroll
                for (int j = 0; j < 4; j++) {
                    float4 kv = *(const float4*)(krow + (j << 2));
                    s = fmaf(qv[4 * j + 0], kv.x, s);
                    s = fmaf(qv[4 * j + 1], kv.y, s);
                    s = fmaf(qv[4 * j + 2], kv.z, s);
                    s = fmaf(qv[4 * j + 3], kv.w, s);
                }
                sb[kk] = s;
            }
            float4 rv = __ldg(res4 + g);
            float4 v;
            v.x = msk ? -1e9f : fmaf(sb[0], 0.25f, rv.x);
            v.y = msk ? -1e9f : fmaf(sb[1], 0.25f, rv.y);
            v.z = msk ? -1e9f : fmaf(sb[2], 0.25f, rv.z);
            v.w = msk ? -1e9f : fmaf(sb[3], 0.25f, rv.w);
            *(float4*)(Sc + sidxS(h, q, g)) = v;
            if (sout) sout[g] = v;
        }
    }
    __syncthreads();   // K consumed, Sc complete

    // P6: V = Xv @ Wv -> C ; then softmax over q per (h,k) column (conflict-free rotation)
    gemm44(A, Bm, C, nullptr, ty, tx);
    {
        const int g = q >> 2, w = q & 3;     // q plays the k role here
        float mx = -3.4e38f;
#pragma unroll 8
        for (int qq = 0; qq < 64; qq++) mx = fmaxf(mx, Sc[sidxS(h, qq, g) + w]);
        float ssum = 0.f;
#pragma unroll 8
        for (int qq = 0; qq < 64; qq++) {
            float* p = Sc + sidxS(h, qq, g) + w;
            float e = __expf(*p - mx);
            *p = e;
            ssum += e;
        }
        float inv = 1.0f / ssum;
#pragma unroll 8
        for (int qq = 0; qq < 64; qq++) Sc[sidxS(h, qq, g) + w] *= inv;
    }
    __syncthreads();

    // P7: stage Wfc (LDGs overlap AV) + ctx = attn @ V -> A (thread=(h,q))
    stageW(Bm, gWfc, tid);
    {
        float acc[16];
#pragma unroll
        for (int j = 0; j < 16; j++) acc[j] = 0.f;
#pragma unroll 4
        for (int g = 0; g < 16; g++) {
            float4 a = *(const float4*)(Sc + sidxS(h, q, g));   // conflict-free
#pragma unroll
            for (int kk = 0; kk < 4; kk++) {
                float av = elem4(a, kk);
                const float* vrow = C + (((g << 2) + kk) << 6) + (h << 4);  // broadcast
#pragma unroll
                for (int j = 0; j < 4; j++) {
                    float4 vv = *(const float4*)(vrow + (j << 2));
                    acc[4 * j + 0] = fmaf(av, vv.x, acc[4 * j + 0]);
                    acc[4 * j + 1] = fmaf(av, vv.y, acc[4 * j + 1]);
                    acc[4 * j + 2] = fmaf(av, vv.z, acc[4 * j + 2]);
                    acc[4 * j + 3] = fmaf(av, vv.w, acc[4 * j + 3]);
                }
            }
        }
#pragma unroll
        for (int j = 0; j < 4; j++)     // ctx row q, cols h*16+4j.. -> pitch AP conflict-free
            *(float4*)(A + q * AP + (h << 4) + (j << 2)) =
                make_float4(acc[4 * j], acc[4 * j + 1], acc[4 * j + 2], acc[4 * j + 3]);
    }
    __syncthreads();

    // P8: y = ctx @ W_fc + input_Q -> C
    gemm44(A, Bm, C, xq, ty, tx);
    __syncthreads();

    // P9: LayerNorm per row (warp-per-row) -> gOut
    {
        const int w = tid >> 5, ln = tid & 31;
        float s0 = __ldg(&gScale[ln]), s1 = __ldg(&gScale[ln + 32]);
        float b0 = __ldg(&gBias[ln]),  b1 = __ldg(&gBias[ln + 32]);
        float* outp = gOut + ((size_t)bn << 12);
#pragma unroll
        for (int rr = w; rr < 64; rr += 8) {
            float v0 = C[(rr << 6) + ln];
            float v1 = C[(rr << 6) + ln + 32];
            float s = v0 + v1;
#pragma unroll
            for (int o = 16; o > 0; o >>= 1) s += __shfl_xor_sync(0xffffffffu, s, o);
            float mu = s * 0.015625f;
            float d0 = v0 - mu, d1 = v1 - mu;
            float vv = d0 * d0 + d1 * d1;
#pragma unroll
            for (int o = 16; o > 0; o >>= 1) vv += __shfl_xor_sync(0xffffffffu, vv, o);
            float inv = rsqrtf(vv * 0.015625f + 1e-5f);
            outp[(rr << 6) + ln]      = fmaf(d0 * inv, s0, b0);
            outp[(rr << 6) + ln + 32] = fmaf(d1 * inv, s1, b1);
        }
    }
}

extern "C" void kernel_launch(void* const* d_in, const int* in_sizes, int n_in,
                              void* d_out, int out_size) {
    const float* gQ = (const float*)d_in[0];
    const float* gK = (const float*)d_in[1];
    const float* gV = (const float*)d_in[2];
    const float* gM = (const float*)d_in[3];
    const float* gR = (const float*)d_in[4];
    const float* wq = (const float*)d_in[5];
    const float* wk = (const float*)d_in[6];
    const float* wv = (const float*)d_in[7];
    const float* wf = (const float*)d_in[8];
    const float* ls = (const float*)d_in[9];
    const float* lb = (const float*)d_in[10];
    float* out = (float*)d_out;

    int write_scores = (out_size >= (int)TOTAL_ELEMS) ? 1 : 0;
    float* scores = out + OUT_ELEMS;

    size_t smem = (size_t)SMEM_FLOATS * sizeof(float);
    cudaFuncSetAttribute(mta_kernel, cudaFuncAttributeMaxDynamicSharedMemorySize, (int)smem);
    mta_kernel<<<NBN, THREADS, smem>>>(gQ, gK, gV, gM, gR, wq, wk, wv, wf, ls, lb,
                                       out, scores, write_scores);
}